// round 16
// baseline (speedup 1.0000x reference)
#include <cuda_runtime.h>
#include <cuda_fp16.h>
#include <math.h>

// ---------------- problem constants ----------------
#define NQ   10000
#define DIM  256
#define NH   8
#define PT   4
#define PP   4
#define NC   6
#define HF   24
#define WF   60
#define BHH  100
#define BWW  100
#define DFF  1024
#define T_RAD 0.15f
#define S_RAD 0.12f

// ---------------- scratch ----------------
__device__ __align__(256) __half g_ai_h[NQ * 512];
__device__ __align__(256) float g_toff[NQ * 128];
__device__ __align__(256) float g_twl[NQ * 64];
__device__ __align__(256) __half g_tfused_h[NQ * DIM];
__device__ __align__(256) float g_x[NQ * DIM];
__device__ __align__(256) __half g_q2_h[NQ * DIM];
__device__ __align__(256) float g_soff[NQ * 256];
__device__ __align__(256) float g_swl[NQ * 128];
__device__ __align__(256) __half g_sfused_h[NQ * DIM];
__device__ __align__(256) float g_x2[NQ * DIM];
__device__ __align__(256) __half g_q3_h[NQ * DIM];
__device__ __align__(256) __half g_h_h[NQ * DFF];
__device__ __align__(256) __half g_feats_h[NC * HF * WF * DIM];
__device__ __align__(256) __half g_w1t[192 * 512];
__device__ __align__(256) float g_b1[192];
__device__ __align__(256) __half g_w2t[384 * 256];
__device__ __align__(256) float g_b2[384];
__device__ __align__(256) __half g_towt[256 * 256];
__device__ __align__(256) __half g_sowt[256 * 256];
__device__ __align__(256) __half g_fw1t[1024 * 256];
__device__ __align__(256) __half g_fw2t[256 * 1024];
__device__ int g_flag_ge2;   // monotonic; same input -> same flags every call
__device__ int g_flag_odd1;

__device__ __forceinline__ float warpSum(float v) {
    #pragma unroll
    for (int o = 16; o > 0; o >>= 1) v += __shfl_xor_sync(0xffffffffu, v, o);
    return v;
}

__device__ __forceinline__ float tanh_fast(float x) {
    asm("tanh.approx.f32 %0, %0;" : "+f"(x));
    return x;
}

// ============================================================================
// MEGA PREP KERNEL: ln1 | feats transpose | weight transposes | bias | detect
// ============================================================================
#define NB_LN1 1250
#define NB_TF  2160
#define NB_WT  832
#define NB_BIA 1

__device__ void do_ln1(int bid, const float* __restrict__ q, const float* __restrict__ p,
                       const float* __restrict__ g, const float* __restrict__ b) {
    int w = threadIdx.x >> 5, lane = threadIdx.x & 31;
    int n = bid * 8 + w;
    const float* qr = q + (size_t)n * DIM;
    const float* pr = p + (size_t)n * DIM;
    float4 q0 = __ldg((const float4*)(qr + lane * 4));
    float4 q1 = __ldg((const float4*)(qr + 128 + lane * 4));
    float4 p0 = __ldg((const float4*)(pr + lane * 4));
    float4 p1 = __ldg((const float4*)(pr + 128 + lane * 4));
    float4 g0 = __ldg((const float4*)(g + lane * 4));
    float4 g1 = __ldg((const float4*)(g + 128 + lane * 4));
    float4 b0 = __ldg((const float4*)(b + lane * 4));
    float4 b1 = __ldg((const float4*)(b + 128 + lane * 4));
    float sq = warpSum(q0.x + q0.y + q0.z + q0.w + q1.x + q1.y + q1.z + q1.w);
    float sp = warpSum(p0.x + p0.y + p0.z + p0.w + p1.x + p1.y + p1.z + p1.w);
    float muq = sq * (1.f / DIM), mup = sp * (1.f / DIM);
    float dq[8] = {q0.x - muq, q0.y - muq, q0.z - muq, q0.w - muq,
                   q1.x - muq, q1.y - muq, q1.z - muq, q1.w - muq};
    float dp[8] = {p0.x - mup, p0.y - mup, p0.z - mup, p0.w - mup,
                   p1.x - mup, p1.y - mup, p1.z - mup, p1.w - mup};
    float vq = 0.f, vp = 0.f;
    #pragma unroll
    for (int i = 0; i < 8; i++) { vq += dq[i] * dq[i]; vp += dp[i] * dp[i]; }
    float rq = rsqrtf(warpSum(vq) * (1.f / DIM) + 1e-5f);
    float rp = rsqrtf(warpSum(vp) * (1.f / DIM) + 1e-5f);
    float gg[8] = {g0.x, g0.y, g0.z, g0.w, g1.x, g1.y, g1.z, g1.w};
    float bb[8] = {b0.x, b0.y, b0.z, b0.w, b1.x, b1.y, b1.z, b1.w};
    __half* ah = g_ai_h + (size_t)n * 512;
    #pragma unroll
    for (int half = 0; half < 2; half++) {
        int off = half * 128 + lane * 4;
        __half2* hp = (__half2*)(ah + off);
        hp[0] = __floats2half2_rn(dp[half*4+0] * rp * gg[half*4+0] + bb[half*4+0],
                                  dp[half*4+1] * rp * gg[half*4+1] + bb[half*4+1]);
        hp[1] = __floats2half2_rn(dp[half*4+2] * rp * gg[half*4+2] + bb[half*4+2],
                                  dp[half*4+3] * rp * gg[half*4+3] + bb[half*4+3]);
        __half2* hq = (__half2*)(ah + 256 + off);
        hq[0] = __floats2half2_rn(dq[half*4+0] * rq * gg[half*4+0] + bb[half*4+0],
                                  dq[half*4+1] * rq * gg[half*4+1] + bb[half*4+1]);
        hq[1] = __floats2half2_rn(dq[half*4+2] * rq * gg[half*4+2] + bb[half*4+2],
                                  dq[half*4+3] * rq * gg[half*4+3] + bb[half*4+3]);
    }
}

__global__ void mega_prep(
    const float* __restrict__ query, const float* __restrict__ prevbev,
    const float* __restrict__ ln1_g, const float* __restrict__ ln1_b,
    const float* __restrict__ imfeats,
    const float* __restrict__ ow1, const float* __restrict__ ob1,
    const float* __restrict__ ww1, const float* __restrict__ wb1,
    const float* __restrict__ ow2, const float* __restrict__ ob2,
    const float* __restrict__ ww2, const float* __restrict__ wb2,
    const float* __restrict__ tow, const float* __restrict__ sow,
    const float* __restrict__ fw1, const float* __restrict__ fw2,
    const unsigned char* __restrict__ mask) {
    int bid = blockIdx.x;
    if (bid < NB_LN1) {
        do_ln1(bid, query, prevbev, ln1_g, ln1_b);
        return;
    }
    bid -= NB_LN1;
    if (bid < NB_TF) {
        __shared__ float tile[32][33];
        int c = bid / 360, rem = bid % 360;
        int ch0 = (rem / 45) * 32, p0 = (rem % 45) * 32;
        int tx = threadIdx.x & 31, ty = threadIdx.x >> 5;
        #pragma unroll
        for (int r = ty; r < 32; r += 8)
            tile[r][tx] = imfeats[((size_t)c * DIM + ch0 + r) * (HF * WF) + p0 + tx];
        __syncthreads();
        #pragma unroll
        for (int r = ty; r < 32; r += 8)
            g_feats_h[((size_t)c * (HF * WF) + p0 + r) * DIM + ch0 + tx] = __float2half(tile[tx][r]);
        return;
    }
    bid -= NB_TF;
    if (bid < NB_WT) {
        __shared__ float tile[32][33];
        int tx = threadIdx.x & 31, ty = threadIdx.x >> 5;
        int task, tb = bid;
        int K, N;
        if (tb < 256)      { task = 0; K = 256;  N = 1024; }
        else if (tb < 512) { task = 1; K = 1024; N = 256;  tb -= 256; }
        else if (tb < 576) { task = 2; K = 256;  N = 256;  tb -= 512; }
        else if (tb < 640) { task = 3; K = 256;  N = 256;  tb -= 576; }
        else if (tb < 736) { task = 4; K = 512;  N = 192;  tb -= 640; }
        else               { task = 5; K = 256;  N = 384;  tb -= 736; }
        int ntn = N >> 5;
        int k0 = (tb / ntn) * 32, n0 = (tb % ntn) * 32;
        #pragma unroll
        for (int r = ty; r < 32; r += 8) {
            int k = k0 + r, n = n0 + tx;
            float v;
            if (task == 0)      v = fw1[(size_t)k * 1024 + n];
            else if (task == 1) v = fw2[(size_t)k * 256 + n];
            else if (task == 2) v = tow[(size_t)k * 256 + n];
            else if (task == 3) v = sow[(size_t)k * 256 + n];
            else if (task == 4) v = (n < 128) ? ow1[(size_t)k * 128 + n] : ww1[(size_t)k * 64 + n - 128];
            else                v = (n < 256) ? ow2[(size_t)k * 256 + n] : ww2[(size_t)k * 128 + n - 256];
            tile[r][tx] = v;
        }
        __syncthreads();
        __half* dst = (task == 0) ? g_fw1t : (task == 1) ? g_fw2t : (task == 2) ? g_towt
                    : (task == 3) ? g_sowt : (task == 4) ? g_w1t : g_w2t;
        #pragma unroll
        for (int r = ty; r < 32; r += 8)
            dst[(size_t)(n0 + r) * K + k0 + tx] = __float2half_rn(tile[tx][r]);
        return;
    }
    bid -= NB_WT;
    if (bid < NB_BIA) {
        int i = threadIdx.x;
        if (i < 192) g_b1[i] = (i < 128) ? ob1[i] : wb1[i - 128];
        for (int j = i; j < 384; j += 256)
            g_b2[j] = (j < 256) ? ob2[j] : wb2[j - 256];
        return;
    }
    bid -= NB_BIA;
    {
        int nbytes = NC * NQ * PP;
        int ge2 = 0, odd1 = 0;
        for (int i = bid * 256 + threadIdx.x; i < nbytes; i += 240 * 256) {
            unsigned char v = mask[i];
            ge2 |= (v >= 2);
            odd1 |= (v == 1 && (i & 3));
        }
        int bge2 = __syncthreads_or(ge2);
        int bodd = __syncthreads_or(odd1);
        if (threadIdx.x == 0) {
            if (bge2) atomicOr(&g_flag_ge2, 1);
            if (bodd) atomicOr(&g_flag_odd1, 1);
        }
    }
}

// ---------------- layernorm (warp-per-row, fp16 out) ----------------
__global__ void ln_kernel(const float* __restrict__ in, const float* __restrict__ g,
                          const float* __restrict__ b, __half* __restrict__ out) {
    int w = threadIdx.x >> 5, lane = threadIdx.x & 31;
    int n = blockIdx.x * 8 + w;
    const float* xr = in + (size_t)n * DIM;
    float4 x0 = __ldg((const float4*)(xr + lane * 4));
    float4 x1 = __ldg((const float4*)(xr + 128 + lane * 4));
    float4 g0 = __ldg((const float4*)(g + lane * 4));
    float4 g1 = __ldg((const float4*)(g + 128 + lane * 4));
    float4 b0 = __ldg((const float4*)(b + lane * 4));
    float4 b1 = __ldg((const float4*)(b + 128 + lane * 4));
    float s = warpSum(x0.x + x0.y + x0.z + x0.w + x1.x + x1.y + x1.z + x1.w);
    float mu = s * (1.f / DIM);
    float d[8] = {x0.x - mu, x0.y - mu, x0.z - mu, x0.w - mu,
                  x1.x - mu, x1.y - mu, x1.z - mu, x1.w - mu};
    float v = 0.f;
    #pragma unroll
    for (int i = 0; i < 8; i++) v += d[i] * d[i];
    float r = rsqrtf(warpSum(v) * (1.f / DIM) + 1e-5f);
    float gg[8] = {g0.x, g0.y, g0.z, g0.w, g1.x, g1.y, g1.z, g1.w};
    float bb[8] = {b0.x, b0.y, b0.z, b0.w, b1.x, b1.y, b1.z, b1.w};
    __half* o = out + (size_t)n * DIM;
    #pragma unroll
    for (int half = 0; half < 2; half++) {
        int off = half * 128 + lane * 4;
        __half2* ho = (__half2*)(o + off);
        ho[0] = __floats2half2_rn(d[half*4+0] * r * gg[half*4+0] + bb[half*4+0],
                                  d[half*4+1] * r * gg[half*4+1] + bb[half*4+1]);
        ho[1] = __floats2half2_rn(d[half*4+2] * r * gg[half*4+2] + bb[half*4+2],
                                  d[half*4+3] * r * gg[half*4+3] + bb[half*4+3]);
    }
}

// ---------------- bilinear gather (8 fp16 channels per lane) ----------------
__device__ __forceinline__ void bilin8(const __half* __restrict__ src, int rstride,
                                       int H, int W, float lx, float ly, float w,
                                       float* a) {
    float ix = lx * W - 0.5f, iy = ly * H - 0.5f;
    float x0f = floorf(ix), y0f = floorf(iy);
    float wx = ix - x0f, wy = iy - y0f;
    int x0 = (int)x0f, y0 = (int)y0f, x1 = x0 + 1, y1 = y0 + 1;
    bool vx0 = (x0 >= 0) & (x0 < W), vx1 = (x1 >= 0) & (x1 < W);
    bool vy0 = (y0 >= 0) & (y0 < H), vy1 = (y1 >= 0) & (y1 < H);
    float v[8] = {0.f, 0.f, 0.f, 0.f, 0.f, 0.f, 0.f, 0.f};
    #pragma unroll
    for (int cy = 0; cy < 2; cy++) {
        bool vy = cy ? vy1 : vy0;
        if (!vy) continue;
        int yy = cy ? y1 : y0;
        float wyc = cy ? wy : (1.f - wy);
        #pragma unroll
        for (int cx = 0; cx < 2; cx++) {
            bool vx = cx ? vx1 : vx0;
            if (!vx) continue;
            int xx = cx ? x1 : x0;
            float c = wyc * (cx ? wx : (1.f - wx));
            uint4 u = __ldg((const uint4*)(src + ((size_t)yy * W + xx) * rstride));
            const __half2* hp = (const __half2*)&u;
            #pragma unroll
            for (int i = 0; i < 4; i++) {
                float2 f = __half22float2(hp[i]);
                v[2*i]   += c * f.x;
                v[2*i+1] += c * f.y;
            }
        }
    }
    #pragma unroll
    for (int i = 0; i < 8; i++) a[i] += w * v[i];
}

// ---------------- temporal deformable sampling (warp-per-query) ------------
__global__ void temporal_kernel(const float* __restrict__ ref2d, const float* __restrict__ ego) {
    int n = blockIdx.x * 8 + (threadIdx.x >> 5);
    int lane = threadIdx.x & 31;
    int head = lane >> 2;               // 4 lanes per head
    int choff = head * 32 + (lane & 3) * 8;
    float rx = __ldg(ref2d + (size_t)n * 2 + 0);
    float ry = __ldg(ref2d + (size_t)n * 2 + 1);
    float a[8] = {0.f, 0.f, 0.f, 0.f, 0.f, 0.f, 0.f, 0.f};
    #pragma unroll
    for (int si = 0; si < 2; si++) {
        float l[PT], mx = -1e30f, se = 0.f;
        #pragma unroll
        for (int pt = 0; pt < PT; pt++) {
            l[pt] = g_twl[(size_t)n * 64 + si * 32 + head * 4 + pt];
            mx = fmaxf(mx, l[pt]);
        }
        #pragma unroll
        for (int pt = 0; pt < PT; pt++) { l[pt] = __expf(l[pt] - mx); se += l[pt]; }
        float inv = 1.f / se;
        float bx = rx + (si == 0 ? __ldg(ego + 0) : 0.f);
        float by = ry + (si == 0 ? __ldg(ego + 1) : 0.f);
        const __half* src = g_ai_h + (si == 0 ? 0 : 256) + choff;
        #pragma unroll
        for (int pt = 0; pt < PT; pt++) {
            float ox = g_toff[(size_t)n * 128 + si * 64 + head * 8 + pt * 2 + 0];
            float oy = g_toff[(size_t)n * 128 + si * 64 + head * 8 + pt * 2 + 1];
            bilin8(src, 512, BHH, BWW, bx + ox, by + oy, l[pt] * inv, a);
        }
    }
    uint4 o;
    __half2* op = (__half2*)&o;
    #pragma unroll
    for (int i = 0; i < 4; i++)
        op[i] = __floats2half2_rn(a[2*i] * 0.5f, a[2*i+1] * 0.5f);
    *(uint4*)&g_tfused_h[(size_t)n * DIM + choff] = o;
}

// ---------------- spatial deformable cross-attention (warp-per-query) ------
__global__ void spatial_kernel(const float* __restrict__ refcam,
                               const unsigned char* __restrict__ mask) {
    int n = blockIdx.x * 8 + (threadIdx.x >> 5);
    int lane = threadIdx.x & 31;
    int head = lane >> 2;
    int choff = head * 32 + (lane & 3) * 8;
    int mode = g_flag_ge2 ? 2 : (g_flag_odd1 ? 0 : 1);
    const float* so = g_soff + (size_t)n * 256 + head * 32;
    const float* wl = g_swl + (size_t)n * 128 + head * 16;
    float a[8] = {0.f, 0.f, 0.f, 0.f, 0.f, 0.f, 0.f, 0.f};
    int cnt = 0;
    for (int c = 0; c < NC; c++) {
        size_t mbase = ((size_t)c * NQ + n) * PP;
        bool vis[PP];
        bool any = false;
        #pragma unroll
        for (int pp = 0; pp < PP; pp++) {
            bool v;
            if (mode == 0)      v = mask[mbase + pp] != 0;
            else if (mode == 1) v = ((const int*)mask)[mbase + pp] != 0;
            else                v = ((const float*)mask)[mbase + pp] != 0.f;
            vis[pp] = v;
            any |= v;
        }
        if (!any) continue;
        cnt++;
        float e[16];
        float mx = -1e30f, se = 0.f;
        #pragma unroll
        for (int p = 0; p < 16; p++) {
            if (vis[p >> 2]) {
                e[p] = wl[p];
                mx = fmaxf(mx, e[p]);
            } else e[p] = -1e30f;
        }
        #pragma unroll
        for (int p = 0; p < 16; p++) {
            e[p] = vis[p >> 2] ? __expf(e[p] - mx) : 0.f;
            se += e[p];
        }
        float inv = 1.f / se;
        const __half* src = g_feats_h + (size_t)c * (HF * WF * DIM) + choff;
        const float* rc = refcam + mbase * 2;
        #pragma unroll
        for (int p = 0; p < 16; p++) {
            if (!vis[p >> 2]) continue;
            int pp = p >> 2;
            float lx = __ldg(rc + pp * 2 + 0) + so[p * 2 + 0];
            float ly = __ldg(rc + pp * 2 + 1) + so[p * 2 + 1];
            bilin8(src, DIM, HF, WF, lx, ly, e[p] * inv, a);
        }
    }
    float rinv = 1.f / (float)(cnt > 0 ? cnt : 1);
    uint4 o;
    __half2* op = (__half2*)&o;
    #pragma unroll
    for (int i = 0; i < 4; i++)
        op[i] = __floats2half2_rn(a[2*i] * rinv, a[2*i+1] * rinv);
    *(uint4*)&g_sfused_h[(size_t)n * DIM + choff] = o;
}

// ---------------- FP16 tensor-core GEMM: 64x64 tiles, 256 threads, GS=4 ----
// 8 warps (4 m x 2 n), warp tile 16x32. mma.m16n8k16, fp32 accumulate.
__device__ __forceinline__ void cp16(unsigned dst, const void* src, bool pred) {
    int sz = pred ? 16 : 0;
    asm volatile("cp.async.cg.shared.global [%0], [%1], 16, %2;"
                 :: "r"(dst), "l"(src), "r"(sz) : "memory");
}

#define GS 4
#define AH 24    // smem row stride in halves (16 data + 8 pad)

__global__ __launch_bounds__(256, 3)
void hgemm(const __half* __restrict__ A, const __half* __restrict__ Bt,
           const float* __restrict__ bias, const float* __restrict__ res,
           float* __restrict__ C, float* __restrict__ C2, __half* __restrict__ Ch,
           int M, int N, int K, int act, float scale, int nsplit) {
    __shared__ __align__(16) __half As[GS][64 * AH];
    __shared__ __align__(16) __half Bs[GS][64 * AH];

    int tid = threadIdx.x;
    int lane = tid & 31, wid = tid >> 5;
    int warp_m = wid & 3;          // 4 m-warps x 16 rows
    int warp_n = wid >> 2;         // 2 n-warps x 32 cols
    int lr = lane >> 2;
    int lc = lane & 3;
    int bm = blockIdx.y * 64;
    int bn = blockIdx.x * 64;

    unsigned as_base, bs_base;
    asm("{ .reg .u64 t; cvta.to.shared.u64 t, %1; cvt.u32.u64 %0, t; }"
        : "=r"(as_base) : "l"(&As[0][0]));
    asm("{ .reg .u64 t; cvta.to.shared.u64 t, %1; cvt.u32.u64 %0, t; }"
        : "=r"(bs_base) : "l"(&Bs[0][0]));

    float acc[4][4];
    #pragma unroll
    for (int nt = 0; nt < 4; nt++)
        #pragma unroll
        for (int r = 0; r < 4; r++) acc[nt][r] = 0.f;

    int idx = tid & 127;
    int row = idx >> 1, ch = idx & 1;   // 64 rows x 2 16B-chunks
    bool isA = tid < 128;
    auto issue = [&](int st, int kt) {
        int k0 = kt << 4;
        if (isA) {
            unsigned d = as_base + (unsigned)(st * 64 * AH + row * AH + ch * 8) * 2u;
            cp16(d, A + (size_t)(bm + row) * K + k0 + ch * 8, bm + row < M);
        } else {
            unsigned d = bs_base + (unsigned)(st * 64 * AH + row * AH + ch * 8) * 2u;
            cp16(d, Bt + (size_t)(bn + row) * K + k0 + ch * 8, true);
        }
    };

    int nk = K >> 4;
    #pragma unroll
    for (int s = 0; s < GS - 1; s++) {
        issue(s, s);
        asm volatile("cp.async.commit_group;" ::: "memory");
    }

    for (int kt = 0; kt < nk; kt++) {
        asm volatile("cp.async.wait_group %0;" :: "n"(GS - 2) : "memory");
        __syncthreads();
        if (kt + GS - 1 < nk) issue((kt + GS - 1) % GS, kt + GS - 1);
        asm volatile("cp.async.commit_group;" ::: "memory");

        int buf = kt % GS;
        const __half* ab = &As[buf][0];
        const __half* bb = &Bs[buf][0];
        unsigned afr[4];
        {
            int r0 = (warp_m * 16 + lr) * AH + lc * 2;
            afr[0] = *(const unsigned*)(ab + r0);
            afr[1] = *(const unsigned*)(ab + r0 + 8 * AH);
            afr[2] = *(const unsigned*)(ab + r0 + 8);
            afr[3] = *(const unsigned*)(ab + r0 + 8 * AH + 8);
        }
        #pragma unroll
        for (int nt = 0; nt < 4; nt++) {
            int c0 = (warp_n * 32 + nt * 8 + lr) * AH + lc * 2;
            unsigned b0 = *(const unsigned*)(bb + c0);
            unsigned b1 = *(const unsigned*)(bb + c0 + 8);
            asm volatile(
                "mma.sync.aligned.m16n8k16.row.col.f32.f16.f16.f32 "
                "{%0,%1,%2,%3}, {%4,%5,%6,%7}, {%8,%9}, {%0,%1,%2,%3};"
                : "+f"(acc[nt][0]), "+f"(acc[nt][1]),
                  "+f"(acc[nt][2]), "+f"(acc[nt][3])
                : "r"(afr[0]), "r"(afr[1]), "r"(afr[2]), "r"(afr[3]),
                  "r"(b0), "r"(b1));
        }
    }

    // ---- epilogue ----
    #pragma unroll
    for (int nt = 0; nt < 4; nt++) {
        int r0 = bm + warp_m * 16 + lr;
        int c0 = bn + warp_n * 32 + nt * 8 + lc * 2;
        #pragma unroll
        for (int half = 0; half < 2; half++) {
            int rw = r0 + half * 8;
            if (rw >= M) continue;
            #pragma unroll
            for (int j = 0; j < 2; j++) {
                int col = c0 + j;
                float v = acc[nt][half * 2 + j] + __ldg(bias + col);
                if (res) v += res[(size_t)rw * N + col];
                if (act == 1) {
                    Ch[(size_t)rw * N + col] = __float2half_rn(fmaxf(v, 0.f));
                } else if (act == 3) {
                    if (col < nsplit)
                        C[(size_t)rw * nsplit + col] = tanh_fast(v) * scale;
                    else
                        C2[(size_t)rw * (N - nsplit) + col - nsplit] = v;
                } else {
                    C[(size_t)rw * N + col] = v;
                }
            }
        }
    }
}

static inline void gemm(const __half* A, const __half* Bt, const float* bias, const float* res,
                        float* C, float* C2, __half* Ch,
                        int M, int N, int K, int act, float scale, int nsplit) {
    dim3 grid(N / 64, (M + 63) / 64);
    hgemm<<<grid, 256>>>(A, Bt, bias, res, C, C2, Ch, M, N, K, act, scale, nsplit);
}

// ---------------- launch ----------------
extern "C" void kernel_launch(void* const* d_in, const int* in_sizes, int n_in,
                              void* d_out, int out_size) {
    const float* query   = (const float*)d_in[0];
    const float* prevbev = (const float*)d_in[1];
    const float* imfeats = (const float*)d_in[2];
    const float* ref2d   = (const float*)d_in[3];
    const float* refcam  = (const float*)d_in[4];
    const float* ego     = (const float*)d_in[5];
    const float* t_off_w = (const float*)d_in[6];
    const float* t_off_b = (const float*)d_in[7];
    const float* t_wt_w  = (const float*)d_in[8];
    const float* t_wt_b  = (const float*)d_in[9];
    const float* t_out_w = (const float*)d_in[10];
    const float* t_out_b = (const float*)d_in[11];
    const float* s_off_w = (const float*)d_in[12];
    const float* s_off_b = (const float*)d_in[13];
    const float* s_wt_w  = (const float*)d_in[14];
    const float* s_wt_b  = (const float*)d_in[15];
    const float* s_out_w = (const float*)d_in[16];
    const float* s_out_b = (const float*)d_in[17];
    const float* ffn_w1  = (const float*)d_in[18];
    const float* ffn_b1  = (const float*)d_in[19];
    const float* ffn_w2  = (const float*)d_in[20];
    const float* ffn_b2  = (const float*)d_in[21];
    const float* ln1_g   = (const float*)d_in[22];
    const float* ln1_b   = (const float*)d_in[23];
    const float* ln2_g   = (const float*)d_in[24];
    const float* ln2_b   = (const float*)d_in[25];
    const float* ln3_g   = (const float*)d_in[26];
    const float* ln3_b   = (const float*)d_in[27];
    const unsigned char* bev_mask = (const unsigned char*)d_in[28];

    __half *aih, *tfh, *q2h, *sfh, *q3h, *hh, *w1t, *w2t, *towt, *sowt, *fw1t, *fw2t;
    float *toff, *twl, *x, *soff, *swl, *x2, *b1, *b2;
    cudaGetSymbolAddress((void**)&aih, g_ai_h);
    cudaGetSymbolAddress((void**)&toff, g_toff);
    cudaGetSymbolAddress((void**)&twl, g_twl);
    cudaGetSymbolAddress((void**)&tfh, g_tfused_h);
    cudaGetSymbolAddress((void**)&x, g_x);
    cudaGetSymbolAddress((void**)&q2h, g_q2_h);
    cudaGetSymbolAddress((void**)&soff, g_soff);
    cudaGetSymbolAddress((void**)&swl, g_swl);
    cudaGetSymbolAddress((void**)&sfh, g_sfused_h);
    cudaGetSymbolAddress((void**)&x2, g_x2);
    cudaGetSymbolAddress((void**)&q3h, g_q3_h);
    cudaGetSymbolAddress((void**)&hh, g_h_h);
    cudaGetSymbolAddress((void**)&w1t, g_w1t);
    cudaGetSymbolAddress((void**)&b1, g_b1);
    cudaGetSymbolAddress((void**)&w2t, g_w2t);
    cudaGetSymbolAddress((void**)&b2, g_b2);
    cudaGetSymbolAddress((void**)&towt, g_towt);
    cudaGetSymbolAddress((void**)&sowt, g_sowt);
    cudaGetSymbolAddress((void**)&fw1t, g_fw1t);
    cudaGetSymbolAddress((void**)&fw2t, g_fw2t);

    // 1) mega prep
    mega_prep<<<NB_LN1 + NB_TF + NB_WT + NB_BIA + 240, 256>>>(
        query, prevbev, ln1_g, ln1_b, imfeats,
        t_off_w, t_off_b, t_wt_w, t_wt_b,
        s_off_w, s_off_b, s_wt_w, s_wt_b,
        t_out_w, s_out_w, ffn_w1, ffn_w2, bev_mask);

    // 2) fused temporal offset+weight projection: N=192 (128 tanh | 64 raw)
    gemm(aih, w1t, b1, nullptr, toff, twl, nullptr, NQ, 192, 512, 3, T_RAD, 128);

    // 3) temporal deformable sampling (warp-per-query)
    temporal_kernel<<<NQ / 8, 256>>>(ref2d, ego);

    // 4) x = query + tfused @ t_out_w + b
    gemm(tfh, towt, t_out_b, query, x, nullptr, nullptr, NQ, DIM, DIM, 0, 0.f, 0);

    // 5) q2 = LN2(x)
    ln_kernel<<<NQ / 8, 256>>>(x, ln2_g, ln2_b, q2h);

    // 6) fused spatial offset+weight projection: N=384 (256 tanh | 128 raw)
    gemm(q2h, w2t, b2, nullptr, soff, swl, nullptr, NQ, 384, 256, 3, S_RAD, 256);

    // 7) spatial deformable cross-attention (warp-per-query)
    spatial_kernel<<<NQ / 8, 256>>>(refcam, bev_mask);

    // 8) x2 = x + sfused @ s_out_w + b
    gemm(sfh, sowt, s_out_b, x, x2, nullptr, nullptr, NQ, DIM, DIM, 0, 0.f, 0);

    // 9) FFN
    ln_kernel<<<NQ / 8, 256>>>(x2, ln3_g, ln3_b, q3h);
    gemm(q3h, fw1t, ffn_b1, nullptr, nullptr, nullptr, hh, NQ, DFF, DIM, 1, 0.f, 0);
    gemm(hh, fw2t, ffn_b2, x2, (float*)d_out, nullptr, nullptr, NQ, DIM, DFF, 0, 0.f, 0);
}

// round 17
// speedup vs baseline: 1.1306x; 1.1306x over previous
#include <cuda_runtime.h>
#include <cuda_fp16.h>
#include <math.h>

// ---------------- problem constants ----------------
#define NQ   10000
#define DIM  256
#define NH   8
#define PT   4
#define PP   4
#define NC   6
#define HF   24
#define WF   60
#define BHH  100
#define BWW  100
#define DFF  1024
#define T_RAD 0.15f
#define S_RAD 0.12f

// ---------------- scratch ----------------
__device__ __align__(256) __half g_ai_h[NQ * 512];
__device__ __align__(256) float g_toff[NQ * 128];
__device__ __align__(256) float g_twl[NQ * 64];
__device__ __align__(256) __half g_tfused_h[NQ * DIM];
__device__ __align__(256) float g_x[NQ * DIM];
__device__ __align__(256) __half g_q2_h[NQ * DIM];
__device__ __align__(256) float g_soff[NQ * 256];
__device__ __align__(256) float g_swl[NQ * 128];
__device__ __align__(256) __half g_sfused_h[NQ * DIM];
__device__ __align__(256) float g_x2[NQ * DIM];
__device__ __align__(256) __half g_q3_h[NQ * DIM];
__device__ __align__(256) __half g_h_h[NQ * DFF];
__device__ __align__(256) __half g_feats_h[NC * HF * WF * DIM];
__device__ __align__(256) __half g_w1t[192 * 512];
__device__ __align__(256) float g_b1[192];
__device__ __align__(256) __half g_w2t[384 * 256];
__device__ __align__(256) float g_b2[384];
__device__ __align__(256) __half g_towt[256 * 256];
__device__ __align__(256) __half g_sowt[256 * 256];
__device__ __align__(256) __half g_fw1t[1024 * 256];
__device__ __align__(256) __half g_fw2t[256 * 1024];
__device__ int g_flag_ge2;   // monotonic; same input -> same flags every call
__device__ int g_flag_odd1;

__device__ __forceinline__ float warpSum(float v) {
    #pragma unroll
    for (int o = 16; o > 0; o >>= 1) v += __shfl_xor_sync(0xffffffffu, v, o);
    return v;
}

__device__ __forceinline__ float tanh_fast(float x) {
    asm("tanh.approx.f32 %0, %0;" : "+f"(x));
    return x;
}

// ============================================================================
// MEGA PREP KERNEL: ln1 | feats transpose | weight transposes | bias | detect
// ============================================================================
#define NB_LN1 1250
#define NB_TF  2160
#define NB_WT  832
#define NB_BIA 1

__device__ void do_ln1(int bid, const float* __restrict__ q, const float* __restrict__ p,
                       const float* __restrict__ g, const float* __restrict__ b) {
    int w = threadIdx.x >> 5, lane = threadIdx.x & 31;
    int n = bid * 8 + w;
    const float* qr = q + (size_t)n * DIM;
    const float* pr = p + (size_t)n * DIM;
    float4 q0 = __ldg((const float4*)(qr + lane * 4));
    float4 q1 = __ldg((const float4*)(qr + 128 + lane * 4));
    float4 p0 = __ldg((const float4*)(pr + lane * 4));
    float4 p1 = __ldg((const float4*)(pr + 128 + lane * 4));
    float4 g0 = __ldg((const float4*)(g + lane * 4));
    float4 g1 = __ldg((const float4*)(g + 128 + lane * 4));
    float4 b0 = __ldg((const float4*)(b + lane * 4));
    float4 b1 = __ldg((const float4*)(b + 128 + lane * 4));
    float sq = warpSum(q0.x + q0.y + q0.z + q0.w + q1.x + q1.y + q1.z + q1.w);
    float sp = warpSum(p0.x + p0.y + p0.z + p0.w + p1.x + p1.y + p1.z + p1.w);
    float muq = sq * (1.f / DIM), mup = sp * (1.f / DIM);
    float dq[8] = {q0.x - muq, q0.y - muq, q0.z - muq, q0.w - muq,
                   q1.x - muq, q1.y - muq, q1.z - muq, q1.w - muq};
    float dp[8] = {p0.x - mup, p0.y - mup, p0.z - mup, p0.w - mup,
                   p1.x - mup, p1.y - mup, p1.z - mup, p1.w - mup};
    float vq = 0.f, vp = 0.f;
    #pragma unroll
    for (int i = 0; i < 8; i++) { vq += dq[i] * dq[i]; vp += dp[i] * dp[i]; }
    float rq = rsqrtf(warpSum(vq) * (1.f / DIM) + 1e-5f);
    float rp = rsqrtf(warpSum(vp) * (1.f / DIM) + 1e-5f);
    float gg[8] = {g0.x, g0.y, g0.z, g0.w, g1.x, g1.y, g1.z, g1.w};
    float bb[8] = {b0.x, b0.y, b0.z, b0.w, b1.x, b1.y, b1.z, b1.w};
    __half* ah = g_ai_h + (size_t)n * 512;
    #pragma unroll
    for (int half = 0; half < 2; half++) {
        int off = half * 128 + lane * 4;
        __half2* hp = (__half2*)(ah + off);
        hp[0] = __floats2half2_rn(dp[half*4+0] * rp * gg[half*4+0] + bb[half*4+0],
                                  dp[half*4+1] * rp * gg[half*4+1] + bb[half*4+1]);
        hp[1] = __floats2half2_rn(dp[half*4+2] * rp * gg[half*4+2] + bb[half*4+2],
                                  dp[half*4+3] * rp * gg[half*4+3] + bb[half*4+3]);
        __half2* hq = (__half2*)(ah + 256 + off);
        hq[0] = __floats2half2_rn(dq[half*4+0] * rq * gg[half*4+0] + bb[half*4+0],
                                  dq[half*4+1] * rq * gg[half*4+1] + bb[half*4+1]);
        hq[1] = __floats2half2_rn(dq[half*4+2] * rq * gg[half*4+2] + bb[half*4+2],
                                  dq[half*4+3] * rq * gg[half*4+3] + bb[half*4+3]);
    }
}

__global__ void mega_prep(
    const float* __restrict__ query, const float* __restrict__ prevbev,
    const float* __restrict__ ln1_g, const float* __restrict__ ln1_b,
    const float* __restrict__ imfeats,
    const float* __restrict__ ow1, const float* __restrict__ ob1,
    const float* __restrict__ ww1, const float* __restrict__ wb1,
    const float* __restrict__ ow2, const float* __restrict__ ob2,
    const float* __restrict__ ww2, const float* __restrict__ wb2,
    const float* __restrict__ tow, const float* __restrict__ sow,
    const float* __restrict__ fw1, const float* __restrict__ fw2,
    const unsigned char* __restrict__ mask) {
    int bid = blockIdx.x;
    if (bid < NB_LN1) {
        do_ln1(bid, query, prevbev, ln1_g, ln1_b);
        return;
    }
    bid -= NB_LN1;
    if (bid < NB_TF) {
        __shared__ float tile[32][33];
        int c = bid / 360, rem = bid % 360;
        int ch0 = (rem / 45) * 32, p0 = (rem % 45) * 32;
        int tx = threadIdx.x & 31, ty = threadIdx.x >> 5;
        #pragma unroll
        for (int r = ty; r < 32; r += 8)
            tile[r][tx] = imfeats[((size_t)c * DIM + ch0 + r) * (HF * WF) + p0 + tx];
        __syncthreads();
        #pragma unroll
        for (int r = ty; r < 32; r += 8)
            g_feats_h[((size_t)c * (HF * WF) + p0 + r) * DIM + ch0 + tx] = __float2half(tile[tx][r]);
        return;
    }
    bid -= NB_TF;
    if (bid < NB_WT) {
        __shared__ float tile[32][33];
        int tx = threadIdx.x & 31, ty = threadIdx.x >> 5;
        int task, tb = bid;
        int K, N;
        if (tb < 256)      { task = 0; K = 256;  N = 1024; }
        else if (tb < 512) { task = 1; K = 1024; N = 256;  tb -= 256; }
        else if (tb < 576) { task = 2; K = 256;  N = 256;  tb -= 512; }
        else if (tb < 640) { task = 3; K = 256;  N = 256;  tb -= 576; }
        else if (tb < 736) { task = 4; K = 512;  N = 192;  tb -= 640; }
        else               { task = 5; K = 256;  N = 384;  tb -= 736; }
        int ntn = N >> 5;
        int k0 = (tb / ntn) * 32, n0 = (tb % ntn) * 32;
        #pragma unroll
        for (int r = ty; r < 32; r += 8) {
            int k = k0 + r, n = n0 + tx;
            float v;
            if (task == 0)      v = fw1[(size_t)k * 1024 + n];
            else if (task == 1) v = fw2[(size_t)k * 256 + n];
            else if (task == 2) v = tow[(size_t)k * 256 + n];
            else if (task == 3) v = sow[(size_t)k * 256 + n];
            else if (task == 4) v = (n < 128) ? ow1[(size_t)k * 128 + n] : ww1[(size_t)k * 64 + n - 128];
            else                v = (n < 256) ? ow2[(size_t)k * 256 + n] : ww2[(size_t)k * 128 + n - 256];
            tile[r][tx] = v;
        }
        __syncthreads();
        __half* dst = (task == 0) ? g_fw1t : (task == 1) ? g_fw2t : (task == 2) ? g_towt
                    : (task == 3) ? g_sowt : (task == 4) ? g_w1t : g_w2t;
        #pragma unroll
        for (int r = ty; r < 32; r += 8)
            dst[(size_t)(n0 + r) * K + k0 + tx] = __float2half_rn(tile[tx][r]);
        return;
    }
    bid -= NB_WT;
    if (bid < NB_BIA) {
        int i = threadIdx.x;
        if (i < 192) g_b1[i] = (i < 128) ? ob1[i] : wb1[i - 128];
        for (int j = i; j < 384; j += 256)
            g_b2[j] = (j < 256) ? ob2[j] : wb2[j - 256];
        return;
    }
    bid -= NB_BIA;
    {
        int nbytes = NC * NQ * PP;
        int ge2 = 0, odd1 = 0;
        for (int i = bid * 256 + threadIdx.x; i < nbytes; i += 240 * 256) {
            unsigned char v = mask[i];
            ge2 |= (v >= 2);
            odd1 |= (v == 1 && (i & 3));
        }
        int bge2 = __syncthreads_or(ge2);
        int bodd = __syncthreads_or(odd1);
        if (threadIdx.x == 0) {
            if (bge2) atomicOr(&g_flag_ge2, 1);
            if (bodd) atomicOr(&g_flag_odd1, 1);
        }
    }
}

// ---------------- layernorm (warp-per-row, fp16 out) ----------------
__global__ void ln_kernel(const float* __restrict__ in, const float* __restrict__ g,
                          const float* __restrict__ b, __half* __restrict__ out) {
    int w = threadIdx.x >> 5, lane = threadIdx.x & 31;
    int n = blockIdx.x * 8 + w;
    const float* xr = in + (size_t)n * DIM;
    float4 x0 = __ldg((const float4*)(xr + lane * 4));
    float4 x1 = __ldg((const float4*)(xr + 128 + lane * 4));
    float4 g0 = __ldg((const float4*)(g + lane * 4));
    float4 g1 = __ldg((const float4*)(g + 128 + lane * 4));
    float4 b0 = __ldg((const float4*)(b + lane * 4));
    float4 b1 = __ldg((const float4*)(b + 128 + lane * 4));
    float s = warpSum(x0.x + x0.y + x0.z + x0.w + x1.x + x1.y + x1.z + x1.w);
    float mu = s * (1.f / DIM);
    float d[8] = {x0.x - mu, x0.y - mu, x0.z - mu, x0.w - mu,
                  x1.x - mu, x1.y - mu, x1.z - mu, x1.w - mu};
    float v = 0.f;
    #pragma unroll
    for (int i = 0; i < 8; i++) v += d[i] * d[i];
    float r = rsqrtf(warpSum(v) * (1.f / DIM) + 1e-5f);
    float gg[8] = {g0.x, g0.y, g0.z, g0.w, g1.x, g1.y, g1.z, g1.w};
    float bb[8] = {b0.x, b0.y, b0.z, b0.w, b1.x, b1.y, b1.z, b1.w};
    __half* o = out + (size_t)n * DIM;
    #pragma unroll
    for (int half = 0; half < 2; half++) {
        int off = half * 128 + lane * 4;
        __half2* ho = (__half2*)(o + off);
        ho[0] = __floats2half2_rn(d[half*4+0] * r * gg[half*4+0] + bb[half*4+0],
                                  d[half*4+1] * r * gg[half*4+1] + bb[half*4+1]);
        ho[1] = __floats2half2_rn(d[half*4+2] * r * gg[half*4+2] + bb[half*4+2],
                                  d[half*4+3] * r * gg[half*4+3] + bb[half*4+3]);
    }
}

// ---------------- bilinear gather (4 fp16 channels per lane) ----------------
__device__ __forceinline__ void bilin4(const __half* __restrict__ src, int rstride,
                                       int H, int W, float lx, float ly, float w,
                                       float* a) {
    float ix = lx * W - 0.5f, iy = ly * H - 0.5f;
    float x0f = floorf(ix), y0f = floorf(iy);
    float wx = ix - x0f, wy = iy - y0f;
    int x0 = (int)x0f, y0 = (int)y0f, x1 = x0 + 1, y1 = y0 + 1;
    bool vx0 = (x0 >= 0) & (x0 < W), vx1 = (x1 >= 0) & (x1 < W);
    bool vy0 = (y0 >= 0) & (y0 < H), vy1 = (y1 >= 0) & (y1 < H);
    float v[4] = {0.f, 0.f, 0.f, 0.f};
    #pragma unroll
    for (int cy = 0; cy < 2; cy++) {
        bool vy = cy ? vy1 : vy0;
        if (!vy) continue;
        int yy = cy ? y1 : y0;
        float wyc = cy ? wy : (1.f - wy);
        #pragma unroll
        for (int cx = 0; cx < 2; cx++) {
            bool vx = cx ? vx1 : vx0;
            if (!vx) continue;
            int xx = cx ? x1 : x0;
            float c = wyc * (cx ? wx : (1.f - wx));
            uint2 u = __ldg((const uint2*)(src + ((size_t)yy * W + xx) * rstride));
            float2 f0 = __half22float2(*(__half2*)&u.x);
            float2 f1 = __half22float2(*(__half2*)&u.y);
            v[0] += c * f0.x; v[1] += c * f0.y;
            v[2] += c * f1.x; v[3] += c * f1.y;
        }
    }
    #pragma unroll
    for (int i = 0; i < 4; i++) a[i] += w * v[i];
}

// ---------------- temporal deformable sampling (4 queries/block) -----------
__global__ void temporal_kernel(const float* __restrict__ ref2d, const float* __restrict__ ego) {
    int n = blockIdx.x * 4 + (threadIdx.x >> 6);
    int sub = threadIdx.x & 63;
    int head = sub >> 3;
    int choff = head * 32 + (sub & 7) * 4;
    float rx = __ldg(ref2d + (size_t)n * 2 + 0);
    float ry = __ldg(ref2d + (size_t)n * 2 + 1);
    float a[4] = {0.f, 0.f, 0.f, 0.f};
    #pragma unroll
    for (int si = 0; si < 2; si++) {
        float l[PT], mx = -1e30f, se = 0.f;
        #pragma unroll
        for (int pt = 0; pt < PT; pt++) {
            l[pt] = g_twl[(size_t)n * 64 + si * 32 + head * 4 + pt];
            mx = fmaxf(mx, l[pt]);
        }
        #pragma unroll
        for (int pt = 0; pt < PT; pt++) { l[pt] = __expf(l[pt] - mx); se += l[pt]; }
        float inv = 1.f / se;
        float bx = rx + (si == 0 ? __ldg(ego + 0) : 0.f);
        float by = ry + (si == 0 ? __ldg(ego + 1) : 0.f);
        const __half* src = g_ai_h + (si == 0 ? 0 : 256) + choff;
        #pragma unroll
        for (int pt = 0; pt < PT; pt++) {
            float ox = g_toff[(size_t)n * 128 + si * 64 + head * 8 + pt * 2 + 0];
            float oy = g_toff[(size_t)n * 128 + si * 64 + head * 8 + pt * 2 + 1];
            bilin4(src, 512, BHH, BWW, bx + ox, by + oy, l[pt] * inv, a);
        }
    }
    __half2 h0 = __floats2half2_rn(a[0] * 0.5f, a[1] * 0.5f);
    __half2 h1 = __floats2half2_rn(a[2] * 0.5f, a[3] * 0.5f);
    uint2 o = make_uint2(*(unsigned*)&h0, *(unsigned*)&h1);
    *(uint2*)&g_tfused_h[(size_t)n * DIM + choff] = o;
}

// ---------------- spatial deformable cross-attention (4 queries/block) -----
__global__ void spatial_kernel(const float* __restrict__ refcam,
                               const unsigned char* __restrict__ mask) {
    int n = blockIdx.x * 4 + (threadIdx.x >> 6);
    int sub = threadIdx.x & 63;
    int head = sub >> 3;
    int choff = head * 32 + (sub & 7) * 4;
    int mode = g_flag_ge2 ? 2 : (g_flag_odd1 ? 0 : 1);
    const float* so = g_soff + (size_t)n * 256 + head * 32;
    const float* wl = g_swl + (size_t)n * 128 + head * 16;
    float a[4] = {0.f, 0.f, 0.f, 0.f};
    int cnt = 0;
    for (int c = 0; c < NC; c++) {
        size_t mbase = ((size_t)c * NQ + n) * PP;
        bool vis[PP];
        bool any = false;
        #pragma unroll
        for (int pp = 0; pp < PP; pp++) {
            bool v;
            if (mode == 0)      v = mask[mbase + pp] != 0;
            else if (mode == 1) v = ((const int*)mask)[mbase + pp] != 0;
            else                v = ((const float*)mask)[mbase + pp] != 0.f;
            vis[pp] = v;
            any |= v;
        }
        if (!any) continue;
        cnt++;
        float e[16];
        float mx = -1e30f, se = 0.f;
        #pragma unroll
        for (int p = 0; p < 16; p++) {
            if (vis[p >> 2]) {
                e[p] = wl[p];
                mx = fmaxf(mx, e[p]);
            } else e[p] = -1e30f;
        }
        #pragma unroll
        for (int p = 0; p < 16; p++) {
            e[p] = vis[p >> 2] ? __expf(e[p] - mx) : 0.f;
            se += e[p];
        }
        float inv = 1.f / se;
        const __half* src = g_feats_h + (size_t)c * (HF * WF * DIM) + choff;
        const float* rc = refcam + mbase * 2;
        #pragma unroll
        for (int p = 0; p < 16; p++) {
            if (!vis[p >> 2]) continue;
            int pp = p >> 2;
            float lx = __ldg(rc + pp * 2 + 0) + so[p * 2 + 0];
            float ly = __ldg(rc + pp * 2 + 1) + so[p * 2 + 1];
            bilin4(src, DIM, HF, WF, lx, ly, e[p] * inv, a);
        }
    }
    float rinv = 1.f / (float)(cnt > 0 ? cnt : 1);
    __half2 h0 = __floats2half2_rn(a[0] * rinv, a[1] * rinv);
    __half2 h1 = __floats2half2_rn(a[2] * rinv, a[3] * rinv);
    uint2 o = make_uint2(*(unsigned*)&h0, *(unsigned*)&h1);
    *(uint2*)&g_sfused_h[(size_t)n * DIM + choff] = o;
}

// ---------------- FP16 tensor-core GEMM: 64x64 tiles, 128 threads, GS=4 ----
// ldmatrix fragment loads: 4 LDSM.x4 per k16 iteration (vs 16 LDS.32).
__device__ __forceinline__ void cp16(unsigned dst, const void* src, bool pred) {
    int sz = pred ? 16 : 0;
    asm volatile("cp.async.cg.shared.global [%0], [%1], 16, %2;"
                 :: "r"(dst), "l"(src), "r"(sz) : "memory");
}

__device__ __forceinline__ void ldsm4(unsigned addr, unsigned& r0, unsigned& r1,
                                      unsigned& r2, unsigned& r3) {
    asm volatile("ldmatrix.sync.aligned.m8n8.x4.shared.b16 {%0,%1,%2,%3}, [%4];"
                 : "=r"(r0), "=r"(r1), "=r"(r2), "=r"(r3) : "r"(addr));
}

#define GS 4
#define AH 24    // smem row stride in halves (16 data + 8 pad); 48B rows -> LDSM conflict-free

__global__ __launch_bounds__(128, 6)
void hgemm(const __half* __restrict__ A, const __half* __restrict__ Bt,
           const float* __restrict__ bias, const float* __restrict__ res,
           float* __restrict__ C, float* __restrict__ C2, __half* __restrict__ Ch,
           int M, int N, int K, int act, float scale, int nsplit) {
    __shared__ __align__(16) __half As[GS][64 * AH];
    __shared__ __align__(16) __half Bs[GS][64 * AH];

    int tid = threadIdx.x;
    int lane = tid & 31, wid = tid >> 5;
    int warp_m = wid & 1;
    int warp_n = wid >> 1;
    int lr = lane >> 2;
    int lc = lane & 3;
    int bm = blockIdx.y * 64;
    int bn = blockIdx.x * 64;

    unsigned as_base, bs_base;
    asm("{ .reg .u64 t; cvta.to.shared.u64 t, %1; cvt.u32.u64 %0, t; }"
        : "=r"(as_base) : "l"(&As[0][0]));
    asm("{ .reg .u64 t; cvta.to.shared.u64 t, %1; cvt.u32.u64 %0, t; }"
        : "=r"(bs_base) : "l"(&Bs[0][0]));

    // ldmatrix per-lane source rows/cols (within the 64xAH tile)
    int a_row[2], b_row[2];
    int a_kc = (lane & 16) >> 1;          // 0 or 8
    int b_kc = lane & 8;                  // 0 or 8
    #pragma unroll
    for (int mt = 0; mt < 2; mt++)
        a_row[mt] = warp_m * 32 + mt * 16 + (lane & 15);
    #pragma unroll
    for (int ntp = 0; ntp < 2; ntp++)
        b_row[ntp] = warp_n * 32 + ntp * 16 + (lane & 7) + ((lane & 16) >> 1);

    float acc[2][4][4];
    #pragma unroll
    for (int mt = 0; mt < 2; mt++)
        #pragma unroll
        for (int nt = 0; nt < 4; nt++)
            #pragma unroll
            for (int r = 0; r < 4; r++) acc[mt][nt][r] = 0.f;

    int arow = tid >> 1, ach = tid & 1;
    auto issue = [&](int st, int kt) {
        int k0 = kt << 4;
        unsigned dA = as_base + (unsigned)(st * 64 * AH + arow * AH + ach * 8) * 2u;
        cp16(dA, A + (size_t)(bm + arow) * K + k0 + ach * 8, bm + arow < M);
        unsigned dB = bs_base + (unsigned)(st * 64 * AH + arow * AH + ach * 8) * 2u;
        cp16(dB, Bt + (size_t)(bn + arow) * K + k0 + ach * 8, true);
    };

    int nk = K >> 4;
    #pragma unroll
    for (int s = 0; s < GS - 1; s++) {
        issue(s, s);
        asm volatile("cp.async.commit_group;" ::: "memory");
    }

    for (int kt = 0; kt < nk; kt++) {
        asm volatile("cp.async.wait_group %0;" :: "n"(GS - 2) : "memory");
        __syncthreads();
        if (kt + GS - 1 < nk) issue((kt + GS - 1) % GS, kt + GS - 1);
        asm volatile("cp.async.commit_group;" ::: "memory");

        int buf = kt % GS;
        unsigned abase = as_base + (unsigned)(buf * 64 * AH) * 2u;
        unsigned bbase = bs_base + (unsigned)(buf * 64 * AH) * 2u;

        unsigned afr[2][4], bfr[2][4];
        #pragma unroll
        for (int mt = 0; mt < 2; mt++)
            ldsm4(abase + (unsigned)(a_row[mt] * AH + a_kc) * 2u,
                  afr[mt][0], afr[mt][1], afr[mt][2], afr[mt][3]);
        #pragma unroll
        for (int ntp = 0; ntp < 2; ntp++)
            ldsm4(bbase + (unsigned)(b_row[ntp] * AH + b_kc) * 2u,
                  bfr[ntp][0], bfr[ntp][1], bfr[ntp][2], bfr[ntp][3]);

        #pragma unroll
        for (int nt = 0; nt < 4; nt++) {
            unsigned b0 = bfr[nt >> 1][(nt & 1) * 2];
            unsigned b1 = bfr[nt >> 1][(nt & 1) * 2 + 1];
            #pragma unroll
            for (int mt = 0; mt < 2; mt++) {
                asm volatile(
                    "mma.sync.aligned.m16n8k16.row.col.f32.f16.f16.f32 "
                    "{%0,%1,%2,%3}, {%4,%5,%6,%7}, {%8,%9}, {%0,%1,%2,%3};"
                    : "+f"(acc[mt][nt][0]), "+f"(acc[mt][nt][1]),
                      "+f"(acc[mt][nt][2]), "+f"(acc[mt][nt][3])
                    : "r"(afr[mt][0]), "r"(afr[mt][1]), "r"(afr[mt][2]), "r"(afr[mt][3]),
                      "r"(b0), "r"(b1));
            }
        }
    }

    // ---- epilogue ----
    #pragma unroll
    for (int mt = 0; mt < 2; mt++) {
        #pragma unroll
        for (int nt = 0; nt < 4; nt++) {
            int r0 = bm + warp_m * 32 + mt * 16 + lr;
            int c0 = bn + warp_n * 32 + nt * 8 + lc * 2;
            #pragma unroll
            for (int half = 0; half < 2; half++) {
                int row = r0 + half * 8;
                if (row >= M) continue;
                #pragma unroll
                for (int j = 0; j < 2; j++) {
                    int col = c0 + j;
                    float v = acc[mt][nt][half * 2 + j] + __ldg(bias + col);
                    if (res) v += res[(size_t)row * N + col];
                    if (act == 1) {
                        Ch[(size_t)row * N + col] = __float2half_rn(fmaxf(v, 0.f));
                    } else if (act == 3) {
                        if (col < nsplit)
                            C[(size_t)row * nsplit + col] = tanh_fast(v) * scale;
                        else
                            C2[(size_t)row * (N - nsplit) + col - nsplit] = v;
                    } else {
                        C[(size_t)row * N + col] = v;
                    }
                }
            }
        }
    }
}

static inline void gemm(const __half* A, const __half* Bt, const float* bias, const float* res,
                        float* C, float* C2, __half* Ch,
                        int M, int N, int K, int act, float scale, int nsplit) {
    dim3 grid(N / 64, (M + 63) / 64);
    hgemm<<<grid, 128>>>(A, Bt, bias, res, C, C2, Ch, M, N, K, act, scale, nsplit);
}

// ---------------- launch ----------------
extern "C" void kernel_launch(void* const* d_in, const int* in_sizes, int n_in,
                              void* d_out, int out_size) {
    const float* query   = (const float*)d_in[0];
    const float* prevbev = (const float*)d_in[1];
    const float* imfeats = (const float*)d_in[2];
    const float* ref2d   = (const float*)d_in[3];
    const float* refcam  = (const float*)d_in[4];
    const float* ego     = (const float*)d_in[5];
    const float* t_off_w = (const float*)d_in[6];
    const float* t_off_b = (const float*)d_in[7];
    const float* t_wt_w  = (const float*)d_in[8];
    const float* t_wt_b  = (const float*)d_in[9];
    const float* t_out_w = (const float*)d_in[10];
    const float* t_out_b = (const float*)d_in[11];
    const float* s_off_w = (const float*)d_in[12];
    const float* s_off_b = (const float*)d_in[13];
    const float* s_wt_w  = (const float*)d_in[14];
    const float* s_wt_b  = (const float*)d_in[15];
    const float* s_out_w = (const float*)d_in[16];
    const float* s_out_b = (const float*)d_in[17];
    const float* ffn_w1  = (const float*)d_in[18];
    const float* ffn_b1  = (const float*)d_in[19];
    const float* ffn_w2  = (const float*)d_in[20];
    const float* ffn_b2  = (const float*)d_in[21];
    const float* ln1_g   = (const float*)d_in[22];
    const float* ln1_b   = (const float*)d_in[23];
    const float* ln2_g   = (const float*)d_in[24];
    const float* ln2_b   = (const float*)d_in[25];
    const float* ln3_g   = (const float*)d_in[26];
    const float* ln3_b   = (const float*)d_in[27];
    const unsigned char* bev_mask = (const unsigned char*)d_in[28];

    __half *aih, *tfh, *q2h, *sfh, *q3h, *hh, *w1t, *w2t, *towt, *sowt, *fw1t, *fw2t;
    float *toff, *twl, *x, *soff, *swl, *x2, *b1, *b2;
    cudaGetSymbolAddress((void**)&aih, g_ai_h);
    cudaGetSymbolAddress((void**)&toff, g_toff);
    cudaGetSymbolAddress((void**)&twl, g_twl);
    cudaGetSymbolAddress((void**)&tfh, g_tfused_h);
    cudaGetSymbolAddress((void**)&x, g_x);
    cudaGetSymbolAddress((void**)&q2h, g_q2_h);
    cudaGetSymbolAddress((void**)&soff, g_soff);
    cudaGetSymbolAddress((void**)&swl, g_swl);
    cudaGetSymbolAddress((void**)&sfh, g_sfused_h);
    cudaGetSymbolAddress((void**)&x2, g_x2);
    cudaGetSymbolAddress((void**)&q3h, g_q3_h);
    cudaGetSymbolAddress((void**)&hh, g_h_h);
    cudaGetSymbolAddress((void**)&w1t, g_w1t);
    cudaGetSymbolAddress((void**)&b1, g_b1);
    cudaGetSymbolAddress((void**)&w2t, g_w2t);
    cudaGetSymbolAddress((void**)&b2, g_b2);
    cudaGetSymbolAddress((void**)&towt, g_towt);
    cudaGetSymbolAddress((void**)&sowt, g_sowt);
    cudaGetSymbolAddress((void**)&fw1t, g_fw1t);
    cudaGetSymbolAddress((void**)&fw2t, g_fw2t);

    // 1) mega prep
    mega_prep<<<NB_LN1 + NB_TF + NB_WT + NB_BIA + 240, 256>>>(
        query, prevbev, ln1_g, ln1_b, imfeats,
        t_off_w, t_off_b, t_wt_w, t_wt_b,
        s_off_w, s_off_b, s_wt_w, s_wt_b,
        t_out_w, s_out_w, ffn_w1, ffn_w2, bev_mask);

    // 2) fused temporal offset+weight projection: N=192 (128 tanh | 64 raw)
    gemm(aih, w1t, b1, nullptr, toff, twl, nullptr, NQ, 192, 512, 3, T_RAD, 128);

    // 3) temporal deformable sampling (4 queries/block)
    temporal_kernel<<<NQ / 4, 256>>>(ref2d, ego);

    // 4) x = query + tfused @ t_out_w + b
    gemm(tfh, towt, t_out_b, query, x, nullptr, nullptr, NQ, DIM, DIM, 0, 0.f, 0);

    // 5) q2 = LN2(x)
    ln_kernel<<<NQ / 8, 256>>>(x, ln2_g, ln2_b, q2h);

    // 6) fused spatial offset+weight projection: N=384 (256 tanh | 128 raw)
    gemm(q2h, w2t, b2, nullptr, soff, swl, nullptr, NQ, 384, 256, 3, S_RAD, 256);

    // 7) spatial deformable cross-attention (4 queries/block)
    spatial_kernel<<<NQ / 4, 256>>>(refcam, bev_mask);

    // 8) x2 = x + sfused @ s_out_w + b
    gemm(sfh, sowt, s_out_b, x, x2, nullptr, nullptr, NQ, DIM, DIM, 0, 0.f, 0);

    // 9) FFN
    ln_kernel<<<NQ / 8, 256>>>(x2, ln3_g, ln3_b, q3h);
    gemm(q3h, fw1t, ffn_b1, nullptr, nullptr, nullptr, hh, NQ, DFF, DIM, 1, 0.f, 0);
    gemm(hh, fw2t, ffn_b2, x2, (float*)d_out, nullptr, nullptr, NQ, DIM, DFF, 0, 0.f, 0);
}